// round 4
// baseline (speedup 1.0000x reference)
#include <cuda_runtime.h>
#include <cuda_bf16.h>
#include <math.h>

#define HF 128
#define WF 128
#define DF 512
#define NA 65536
#define MAXDET 512
#define HIDDEN 1024
#define PDIM (9*512)   // 4608
#define NCAND 4096

typedef unsigned long long u64;
typedef unsigned int u32;

// ---------------- device scratch (static, no allocation) ----------------
__device__ __align__(16) u64   g_keys[NA];
__device__ __align__(16) u32   g_hist[65536 + 2];   // [65536]=compact counter, [65537]=threshold bin
__device__ __align__(16) u64   g_cand[NCAND];
__device__ __align__(16) float g_sel[MAXDET*4];
__device__ float g_scores[MAXDET];
__device__ int   g_valid[MAXDET];
__device__ int   g_keep[MAXDET];

// bf16 hi/lo split activations & weights
__device__ __align__(16) __nv_bfloat16 g_Ahi[MAXDET*PDIM];
__device__ __align__(16) __nv_bfloat16 g_Alo[MAXDET*PDIM];
__device__ __align__(16) __nv_bfloat16 g_W1Th[HIDDEN*PDIM];
__device__ __align__(16) __nv_bfloat16 g_W1Tl[HIDDEN*PDIM];
__device__ __align__(16) __nv_bfloat16 g_W2Th[HIDDEN*HIDDEN];
__device__ __align__(16) __nv_bfloat16 g_W2Tl[HIDDEN*HIDDEN];
__device__ __align__(16) __nv_bfloat16 g_h1hi[MAXDET*HIDDEN];
__device__ __align__(16) __nv_bfloat16 g_h1lo[MAXDET*HIDDEN];
__device__ __align__(16) __nv_bfloat16 g_h2hi[MAXDET*HIDDEN];
__device__ __align__(16) __nv_bfloat16 g_h2lo[MAXDET*HIDDEN];

// ---------------- low-level helpers (plain sm_103-legal PTX only) ----------------
__device__ __forceinline__ u32 smem_u32(const void* p) {
    u32 a;
    asm("{ .reg .u64 t; cvta.to.shared.u64 t, %1; cvt.u32.u64 %0, t; }" : "=r"(a) : "l"(p));
    return a;
}
#define CPA16(dst, src) \
    asm volatile("cp.async.cg.shared.global [%0], [%1], 16;" :: "r"(dst), "l"(src) : "memory")
#define CPA_COMMIT() asm volatile("cp.async.commit_group;" ::: "memory")
#define CPA_WAIT0()  asm volatile("cp.async.wait_group 0;" ::: "memory")

__device__ __forceinline__ void ldsm4(u32* r, u32 addr) {
    asm volatile("ldmatrix.sync.aligned.m8n8.x4.shared.b16 {%0,%1,%2,%3}, [%4];"
                 : "=r"(r[0]), "=r"(r[1]), "=r"(r[2]), "=r"(r[3]) : "r"(addr));
}
__device__ __forceinline__ void ldsm2(u32* r, u32 addr) {
    asm volatile("ldmatrix.sync.aligned.m8n8.x2.shared.b16 {%0,%1}, [%2];"
                 : "=r"(r[0]), "=r"(r[1]) : "r"(addr));
}
__device__ __forceinline__ void mma16816(float* d, const u32* a, const u32* b) {
    asm volatile("mma.sync.aligned.m16n8k16.row.col.f32.bf16.bf16.f32 "
                 "{%0,%1,%2,%3}, {%4,%5,%6,%7}, {%8,%9}, {%0,%1,%2,%3};"
                 : "+f"(d[0]), "+f"(d[1]), "+f"(d[2]), "+f"(d[3])
                 : "r"(a[0]), "r"(a[1]), "r"(a[2]), "r"(a[3]), "r"(b[0]), "r"(b[1]));
}

// ---------------- 1) scores + keys + top-16-bit histogram ----------------
__global__ void score_kernel(const float* __restrict__ obj, u64* __restrict__ keys,
                             u32* __restrict__ hist) {
    int n = blockIdx.x * 256 + threadIdx.x;
    int cell = n >> 2;
    int k = n & 3;
    float o0 = obj[cell*8 + 2*k];
    float o1 = obj[cell*8 + 2*k + 1];
    float m  = fmaxf(o0, o1);
    float e0 = expf(o0 - m);
    float e1 = expf(o1 - m);
    float s  = e1 / (e0 + e1);
    u32 bits = (s > 0.5f) ? __float_as_uint(s) : __float_as_uint(-INFINITY);
    u32 mono = (bits & 0x80000000u) ? ~bits : (bits | 0x80000000u);
    u64 key = ((u64)mono << 32) | (u32)(~n);   // unique; ties -> lower index first
    keys[n] = key;
    atomicAdd(&hist[(u32)(key >> 48)], 1u);
}

// ---------------- 2) find threshold bin for rank-512 ----------------
__global__ void __launch_bounds__(1024) scan_kernel(u32* __restrict__ hist) {
    __shared__ u32 ps[1024];
    int t = threadIdx.x;
    int base = 65535 - 64*t;          // segment scans downward from here
    u32 s = 0;
    #pragma unroll 8
    for (int k = 0; k < 64; k++) s += hist[base - k];
    ps[t] = s;
    __syncthreads();
    // inclusive prefix (from top segment down)
    for (int off = 1; off < 1024; off <<= 1) {
        u32 y = (t >= off) ? ps[t - off] : 0;
        __syncthreads();
        ps[t] += y;
        __syncthreads();
    }
    u32 inc = ps[t];
    u32 exc = inc - s;
    if (exc < 512 && inc >= 512) {     // rank-512 falls in my segment
        u32 c = exc;
        for (int k = 0; k < 64; k++) {
            int b = base - k;
            c += hist[b];
            if (c >= 512) { hist[65537] = (u32)b; break; }
        }
    }
}

// ---------------- 3) compact candidates (bins >= threshold) ----------------
__global__ void compact_kernel(const u64* __restrict__ keys, u32* __restrict__ hist,
                               u64* __restrict__ cand) {
    int n = blockIdx.x * 256 + threadIdx.x;
    u64 key = keys[n];
    if ((u32)(key >> 48) >= hist[65537]) {
        u32 p = atomicAdd(&hist[65536], 1u);
        if (p < NCAND) cand[p] = key;
    }
}

// ---------------- 4) sort candidates + gather/decode top-512 ----------------
__global__ void __launch_bounds__(1024) sortgather_kernel(const u64* __restrict__ cand,
                                                          const u32* __restrict__ hist,
                                                          const float* __restrict__ reg) {
    __shared__ u64 s[NCAND];
    int tid = threadIdx.x;
    u32 cn = hist[65536];
    if (cn > NCAND) cn = NCAND;
    #pragma unroll
    for (int v = 0; v < 4; v++) {
        int i = tid + v*1024;
        s[i] = (i < (int)cn) ? cand[i] : 0ULL;
    }
    __syncthreads();
    for (int k = 2; k <= NCAND; k <<= 1) {
        for (int j = k >> 1; j > 0; j >>= 1) {
            #pragma unroll
            for (int v = 0; v < 4; v++) {
                int i = tid + v*1024;
                int ixj = i ^ j;
                if (ixj > i) {
                    u64 a = s[i], b = s[ixj];
                    bool desc = ((i & k) == 0);
                    if (desc ? (a < b) : (a > b)) { s[i] = b; s[ixj] = a; }
                }
            }
            __syncthreads();
        }
    }
    if (tid < 512) {
        u64 key = s[tid];
        u32 lo = (u32)key;
        u32 hi = (u32)(key >> 32);
        u32 n  = ~lo;
        u32 fb = (hi & 0x80000000u) ? (hi ^ 0x80000000u) : ~hi;
        float score = __uint_as_float(fb);
        int k = n & 3;
        int j = (n >> 2) & 127;
        int i = n >> 9;
        float sz = (float)((k + 1) * 32);
        int base = ((i*128 + j) * 16) + k*4;
        float r0 = reg[base+0], r1 = reg[base+1], r2 = reg[base+2], r3 = reg[base+3];
        float acx = j * 16.0f + 8.0f;
        float acy = i * 16.0f + 8.0f;
        float cx = acx + r0 * sz;
        float cy = acy + r1 * sz;
        float w  = sz * expf(r2);
        float h  = sz * expf(r3);
        g_sel[tid*4+0] = cx - w * 0.5f;
        g_sel[tid*4+1] = cy - h * 0.5f;
        g_sel[tid*4+2] = w;
        g_sel[tid*4+3] = h;
        bool valid = (score > 0.5f);
        g_scores[tid] = valid ? score : 0.0f;
        g_valid[tid]  = valid ? 1 : 0;
    }
}

// ---------------- 5) fused IoU matrix + greedy NMS scan ----------------
__global__ void __launch_bounds__(1024) iou_nms_kernel() {
    __shared__ float4 bx[512];
    __shared__ u32 msk[512][16];
    __shared__ int sval[512];
    int tid = threadIdx.x, lane = tid & 31, w = tid >> 5;
    if (tid < 512) {
        bx[tid] = ((const float4*)g_sel)[tid];
        sval[tid] = g_valid[tid];
    }
    __syncthreads();
    #pragma unroll 1
    for (int r = 0; r < 16; r++) {
        int i = w*16 + r;
        float4 a = bx[i];
        float ax2 = a.x + a.z, ay2 = a.y + a.w, aar = a.z * a.w;
        #pragma unroll 1
        for (int jc = 0; jc < 16; jc++) {
            int j = jc*32 + lane;
            float4 b = bx[j];
            float bx2 = b.x + b.z, by2 = b.y + b.w;
            float ix = fmaxf(0.0f, fminf(ax2, bx2) - fmaxf(a.x, b.x));
            float iy = fmaxf(0.0f, fminf(ay2, by2) - fmaxf(a.y, b.y));
            float inter = ix * iy;
            float iou = inter / (aar + b.z*b.w - inter + 1e-8f);
            u32 bits = __ballot_sync(0xffffffffu, iou > 0.3f);
            if (lane == jc) msk[i][jc] = bits;
        }
    }
    __syncthreads();
    if (w == 0) {
        u32 removed = 0;   // lane l (<16) owns 32-bit word l of the suppression set
        for (int i = 0; i < 512; i++) {
            int wi = i >> 5, bi = i & 31;
            u32 rword = __shfl_sync(0xffffffffu, removed, wi);
            int k = sval[i] && !((rword >> bi) & 1u);
            if (lane == 0) g_keep[i] = k;
            if (k && lane < 16) removed |= msk[i][lane];
        }
    }
}

// ---------------- 6) ROI align -> bf16 hi/lo ----------------
__global__ void __launch_bounds__(512) roi_kernel(const float* __restrict__ feat) {
    int mrow = blockIdx.x;
    __shared__ float bxs[4];
    __shared__ int   xs0[6], xs1[6], ys0[6], ys1[6];
    __shared__ float wxs[6], wys[6];
    int tid = threadIdx.x;
    if (tid < 4) bxs[tid] = g_sel[mrow*4 + tid];
    __syncthreads();
    if (tid < 6) {
        float t = (tid + 0.5f) / 6.0f;
        float fx = (bxs[0] + t * bxs[2]) / 16.0f - 0.5f;
        float fy = (bxs[1] + t * bxs[3]) / 16.0f - 0.5f;
        fx = fminf(fmaxf(fx, 0.0f), 127.0f);
        fy = fminf(fmaxf(fy, 0.0f), 127.0f);
        int x0 = (int)floorf(fx);
        int y0 = (int)floorf(fy);
        xs0[tid] = x0; xs1[tid] = min(x0 + 1, 127); wxs[tid] = fx - (float)x0;
        ys0[tid] = y0; ys1[tid] = min(y0 + 1, 127); wys[tid] = fy - (float)y0;
    }
    __syncthreads();
    int c = tid;
    float mx[9];
    #pragma unroll
    for (int p = 0; p < 9; p++) mx[p] = -INFINITY;
    #pragma unroll
    for (int ty = 0; ty < 6; ty++) {
        int y0 = ys0[ty], y1 = ys1[ty];
        float wy = wys[ty], wy0 = 1.0f - wy;
        #pragma unroll
        for (int tx = 0; tx < 6; tx++) {
            int x0 = xs0[tx], x1 = xs1[tx];
            float wx = wxs[tx], wx0 = 1.0f - wx;
            float f00 = feat[(y0*128 + x0)*512 + c];
            float f01 = feat[(y0*128 + x1)*512 + c];
            float f10 = feat[(y1*128 + x0)*512 + c];
            float f11 = feat[(y1*128 + x1)*512 + c];
            float v = f00*wy0*wx0 + f01*wy0*wx + f10*wy*wx0 + f11*wy*wx;
            int p = (ty >> 1)*3 + (tx >> 1);
            mx[p] = fmaxf(mx[p], v);
        }
    }
    #pragma unroll
    for (int p = 0; p < 9; p++) {
        float v = mx[p];
        __nv_bfloat16 h = __float2bfloat16(v);
        __nv_bfloat16 l = __float2bfloat16(v - __bfloat162float(h));
        g_Ahi[mrow*PDIM + p*512 + c] = h;
        g_Alo[mrow*PDIM + p*512 + c] = l;
    }
}

// ---------------- 7) weight transpose + hi/lo split ----------------
__global__ void tsplit_kernel(const float* __restrict__ W,
                              __nv_bfloat16* __restrict__ Th,
                              __nv_bfloat16* __restrict__ Tl,
                              int K, int N) {
    __shared__ float t[32][33];
    int n0 = blockIdx.x * 32, k0 = blockIdx.y * 32;
    int tx = threadIdx.x, ty = threadIdx.y;   // 32 x 8
    #pragma unroll
    for (int i = 0; i < 4; i++)
        t[ty + 8*i][tx] = W[(size_t)(k0 + ty + 8*i)*N + n0 + tx];
    __syncthreads();
    #pragma unroll
    for (int i = 0; i < 4; i++) {
        float v = t[tx][ty + 8*i];
        __nv_bfloat16 h = __float2bfloat16(v);
        __nv_bfloat16 l = __float2bfloat16(v - __bfloat162float(h));
        size_t o = (size_t)(n0 + ty + 8*i)*K + k0 + tx;
        Th[o] = h;
        Tl[o] = l;
    }
}

// ---------------- 8) HMMA bf16x3 GEMM: C = relu(A@B^T + bias) -> bf16 hi/lo ----------------
// BM=64, BN=64, BK=32, 256 threads, warp grid 2x4, warp tile 32x16.
#define BM 64
#define BN 64
#define BK 32
#define SSTR 40
#define AH0 0
#define AL0 (64*SSTR)
#define BH0 (128*SSTR)
#define BL0 (192*SSTR)
#define BUFE (256*SSTR)        // 10240 elems
#define BUFB (BUFE*2)          // 20480 bytes
#define GEMM_SMEM (2*BUFB)     // 40960 bytes

__device__ __forceinline__ void gemm_load_chunk(u32 smbase, int buf,
    const __nv_bfloat16* __restrict__ Ah, const __nv_bfloat16* __restrict__ Al,
    const __nv_bfloat16* __restrict__ Bh, const __nv_bfloat16* __restrict__ Bl,
    int br, int bc, int K, int k0, int tid)
{
    u32 base = smbase + (u32)buf * BUFB;
    int row = tid >> 2;          // 0..63
    int cg  = (tid & 3) * 8;     // 0,8,16,24
    CPA16(base + (u32)(AH0 + row*SSTR + cg)*2, Ah + (size_t)(br+row)*K + k0 + cg);
    CPA16(base + (u32)(AL0 + row*SSTR + cg)*2, Al + (size_t)(br+row)*K + k0 + cg);
    CPA16(base + (u32)(BH0 + row*SSTR + cg)*2, Bh + (size_t)(bc+row)*K + k0 + cg);
    CPA16(base + (u32)(BL0 + row*SSTR + cg)*2, Bl + (size_t)(bc+row)*K + k0 + cg);
    CPA_COMMIT();
}

__global__ void __launch_bounds__(256) hgemm_kernel(
    const __nv_bfloat16* __restrict__ Ah, const __nv_bfloat16* __restrict__ Al,
    const __nv_bfloat16* __restrict__ Bh, const __nv_bfloat16* __restrict__ Bl,
    const float* __restrict__ bias,
    __nv_bfloat16* __restrict__ Chi, __nv_bfloat16* __restrict__ Clo,
    int K, int ldc, int do_relu)
{
    extern __shared__ __nv_bfloat16 sm[];
    u32 smbase = smem_u32(sm);
    int tid = threadIdx.x;
    int lane = tid & 31;
    int w = tid >> 5;
    int br = blockIdx.y * BM;
    int bc = blockIdx.x * BN;
    int wm = (w >> 2) * 32;        // 2 warps in M
    int wn = (w & 3) * 16;         // 4 warps in N

    float acc[2][2][4];
    #pragma unroll
    for (int mt = 0; mt < 2; mt++)
        #pragma unroll
        for (int nt = 0; nt < 2; nt++)
            #pragma unroll
            for (int e = 0; e < 4; e++) acc[mt][nt][e] = 0.0f;

    const int NC = K / BK;
    gemm_load_chunk(smbase, 0, Ah, Al, Bh, Bl, br, bc, K, 0, tid);

    for (int c = 0; c < NC; c++) {
        CPA_WAIT0();
        __syncthreads();
        if (c + 1 < NC)
            gemm_load_chunk(smbase, (c+1) & 1, Ah, Al, Bh, Bl, br, bc, K, (c+1)*BK, tid);

        u32 base = smbase + (u32)(c & 1) * BUFB;
        #pragma unroll
        for (int ks = 0; ks < BK; ks += 16) {
            u32 afr[2][4], afl[2][4], bfr[2][2], bfl[2][2];
            #pragma unroll
            for (int mt = 0; mt < 2; mt++) {
                u32 ra = base + (u32)(AH0 + (wm + mt*16 + (lane & 15))*SSTR
                                       + ks + (lane >> 4)*8)*2;
                ldsm4(afr[mt], ra);
                ldsm4(afl[mt], ra + (u32)(AL0 - AH0)*2);
            }
            #pragma unroll
            for (int nt = 0; nt < 2; nt++) {
                u32 rb = base + (u32)(BH0 + (wn + nt*8 + (lane & 7))*SSTR
                                       + ks + ((lane >> 3) & 1)*8)*2;
                ldsm2(bfr[nt], rb);
                ldsm2(bfl[nt], rb + (u32)(BL0 - BH0)*2);
            }
            #pragma unroll
            for (int mt = 0; mt < 2; mt++)
                #pragma unroll
                for (int nt = 0; nt < 2; nt++) {
                    mma16816(acc[mt][nt], afr[mt], bfr[nt]);   // Ah*Bh
                    mma16816(acc[mt][nt], afr[mt], bfl[nt]);   // Ah*Bl
                    mma16816(acc[mt][nt], afl[mt], bfr[nt]);   // Al*Bh
                }
        }
        __syncthreads();
    }

    int g  = lane >> 2;
    int tg = lane & 3;
    #pragma unroll
    for (int mt = 0; mt < 2; mt++) {
        #pragma unroll
        for (int nt = 0; nt < 2; nt++) {
            int row0 = br + wm + mt*16 + g;
            int col0 = bc + wn + nt*8 + 2*tg;
            #pragma unroll
            for (int e = 0; e < 4; e++) {
                int row = row0 + (e >> 1)*8;
                int col = col0 + (e & 1);
                float v = acc[mt][nt][e] + bias[col];
                if (do_relu) v = fmaxf(v, 0.0f);
                __nv_bfloat16 h = __float2bfloat16(v);
                __nv_bfloat16 l = __float2bfloat16(v - __bfloat162float(h));
                Chi[(size_t)row*ldc + col] = h;
                Clo[(size_t)row*ldc + col] = l;
            }
        }
    }
}

// ---------------- 9) FC3 + unparameterize + keep gate ----------------
__global__ void fc3_final_kernel(const float* __restrict__ W3,
                                 const float* __restrict__ b3,
                                 float* __restrict__ out) {
    int mrow = blockIdx.x;
    int tid = threadIdx.x;     // 128
    float acc[4] = {0,0,0,0};
    for (int k = tid; k < HIDDEN; k += 128) {
        float hv = __bfloat162float(g_h2hi[mrow*HIDDEN + k]) +
                   __bfloat162float(g_h2lo[mrow*HIDDEN + k]);
        #pragma unroll
        for (int c = 0; c < 4; c++) acc[c] = fmaf(hv, W3[k*4 + c], acc[c]);
    }
    __shared__ float red[4][128];
    #pragma unroll
    for (int c = 0; c < 4; c++) red[c][tid] = acc[c];
    __syncthreads();
    for (int s = 64; s > 0; s >>= 1) {
        if (tid < s) {
            #pragma unroll
            for (int c = 0; c < 4; c++) red[c][tid] += red[c][tid + s];
        }
        __syncthreads();
    }
    if (tid == 0) {
        if (!g_keep[mrow]) {
            #pragma unroll
            for (int c = 0; c < 5; c++) out[mrow*5 + c] = 0.0f;
        } else {
            float d0 = red[0][0] + b3[0];
            float d1 = red[1][0] + b3[1];
            float d2 = red[2][0] + b3[2];
            float d3 = red[3][0] + b3[3];
            float sx = g_sel[mrow*4+0], sy = g_sel[mrow*4+1];
            float sw = g_sel[mrow*4+2], sh = g_sel[mrow*4+3];
            float acx = sx + sw * 0.5f;
            float acy = sy + sh * 0.5f;
            float cx = acx + d0 * sw;
            float cy = acy + d1 * sh;
            float w  = sw * expf(d2);
            float h  = sh * expf(d3);
            out[mrow*5+0] = cx - w * 0.5f;
            out[mrow*5+1] = cy - h * 0.5f;
            out[mrow*5+2] = w;
            out[mrow*5+3] = h;
            out[mrow*5+4] = g_scores[mrow];
        }
    }
}

// ---------------- launch ----------------
extern "C" void kernel_launch(void* const* d_in, const int* in_sizes, int n_in,
                              void* d_out, int out_size) {
    const float* features = (const float*)d_in[0];
    const float* rpn_obj  = (const float*)d_in[1];
    const float* rpn_reg  = (const float*)d_in[2];
    const float* W1 = (const float*)d_in[4];
    const float* b1 = (const float*)d_in[5];
    const float* W2 = (const float*)d_in[6];
    const float* b2 = (const float*)d_in[7];
    const float* W3 = (const float*)d_in[8];
    const float* b3 = (const float*)d_in[9];
    float* out = (float*)d_out;

    u64 *keys, *cand;
    u32 *hist;
    __nv_bfloat16 *Ahi, *Alo, *W1Th, *W1Tl, *W2Th, *W2Tl, *h1hi, *h1lo, *h2hi, *h2lo;
    cudaGetSymbolAddress((void**)&keys, g_keys);
    cudaGetSymbolAddress((void**)&cand, g_cand);
    cudaGetSymbolAddress((void**)&hist, g_hist);
    cudaGetSymbolAddress((void**)&Ahi, g_Ahi);
    cudaGetSymbolAddress((void**)&Alo, g_Alo);
    cudaGetSymbolAddress((void**)&W1Th, g_W1Th);
    cudaGetSymbolAddress((void**)&W1Tl, g_W1Tl);
    cudaGetSymbolAddress((void**)&W2Th, g_W2Th);
    cudaGetSymbolAddress((void**)&W2Tl, g_W2Tl);
    cudaGetSymbolAddress((void**)&h1hi, g_h1hi);
    cudaGetSymbolAddress((void**)&h1lo, g_h1lo);
    cudaGetSymbolAddress((void**)&h2hi, g_h2hi);
    cudaGetSymbolAddress((void**)&h2lo, g_h2lo);

    cudaFuncSetAttribute(hgemm_kernel,
                         cudaFuncAttributeMaxDynamicSharedMemorySize, GEMM_SMEM);

    cudaMemsetAsync(hist, 0, (65536 + 2) * sizeof(u32));

    // weight prep (independent of detection path)
    tsplit_kernel<<<dim3(HIDDEN/32, PDIM/32),   dim3(32,8)>>>(W1, W1Th, W1Tl, PDIM,   HIDDEN);
    tsplit_kernel<<<dim3(HIDDEN/32, HIDDEN/32), dim3(32,8)>>>(W2, W2Th, W2Tl, HIDDEN, HIDDEN);

    score_kernel<<<NA/256, 256>>>(rpn_obj, keys, hist);
    scan_kernel<<<1, 1024>>>(hist);
    compact_kernel<<<NA/256, 256>>>(keys, hist, cand);
    sortgather_kernel<<<1, 1024>>>(cand, hist, rpn_reg);

    roi_kernel<<<512, 512>>>(features);
    iou_nms_kernel<<<1, 1024>>>();

    dim3 gg(HIDDEN/BN, MAXDET/BM);   // 16 x 8 = 128 CTAs
    hgemm_kernel<<<gg, 256, GEMM_SMEM>>>(Ahi,  Alo,  W1Th, W1Tl, b1, h1hi, h1lo,
                                         PDIM,   HIDDEN, 1);
    hgemm_kernel<<<gg, 256, GEMM_SMEM>>>(h1hi, h1lo, W2Th, W2Tl, b2, h2hi, h2lo,
                                         HIDDEN, HIDDEN, 1);
    fc3_final_kernel<<<MAXDET, 128>>>(W3, b3, out);
}

// round 5
// speedup vs baseline: 1.2731x; 1.2731x over previous
#include <cuda_runtime.h>
#include <cuda_bf16.h>
#include <math.h>

#define HF 128
#define WF 128
#define DF 512
#define NA 65536
#define MAXDET 512
#define HIDDEN 1024
#define PDIM (9*512)   // 4608
#define NBIN 16384
#define NCAND 1024

typedef unsigned long long u64;
typedef unsigned int u32;

// hist layout: [0..16383] bins, [16384]=threshold bin, [16385]=total valid, [16386]=compact counter
#define H_THR  16384
#define H_TOT  16385
#define H_CNT  16386

// ---------------- device scratch (static, no allocation) ----------------
__device__ __align__(16) u64   g_keys[NA];
__device__ __align__(16) u32   g_hist[NBIN + 8];
__device__ __align__(16) u64   g_cand[NCAND];
__device__ __align__(16) float g_sel[MAXDET*4];
__device__ float g_scores[MAXDET];
__device__ int   g_keep[MAXDET];

// bf16 hi/lo split activations & weights
__device__ __align__(16) __nv_bfloat16 g_Ahi[MAXDET*PDIM];
__device__ __align__(16) __nv_bfloat16 g_Alo[MAXDET*PDIM];
__device__ __align__(16) __nv_bfloat16 g_W1Th[HIDDEN*PDIM];
__device__ __align__(16) __nv_bfloat16 g_W1Tl[HIDDEN*PDIM];
__device__ __align__(16) __nv_bfloat16 g_W2Th[HIDDEN*HIDDEN];
__device__ __align__(16) __nv_bfloat16 g_W2Tl[HIDDEN*HIDDEN];
__device__ __align__(16) __nv_bfloat16 g_h1hi[MAXDET*HIDDEN];
__device__ __align__(16) __nv_bfloat16 g_h1lo[MAXDET*HIDDEN];
__device__ __align__(16) __nv_bfloat16 g_h2hi[MAXDET*HIDDEN];
__device__ __align__(16) __nv_bfloat16 g_h2lo[MAXDET*HIDDEN];

// ---------------- low-level helpers (plain sm_103-legal PTX only) ----------------
__device__ __forceinline__ u32 smem_u32(const void* p) {
    u32 a;
    asm("{ .reg .u64 t; cvta.to.shared.u64 t, %1; cvt.u32.u64 %0, t; }" : "=r"(a) : "l"(p));
    return a;
}
#define CPA16(dst, src) \
    asm volatile("cp.async.cg.shared.global [%0], [%1], 16;" :: "r"(dst), "l"(src) : "memory")
#define CPA_COMMIT() asm volatile("cp.async.commit_group;" ::: "memory")
#define CPA_WAIT0()  asm volatile("cp.async.wait_group 0;" ::: "memory")

__device__ __forceinline__ void ldsm4(u32* r, u32 addr) {
    asm volatile("ldmatrix.sync.aligned.m8n8.x4.shared.b16 {%0,%1,%2,%3}, [%4];"
                 : "=r"(r[0]), "=r"(r[1]), "=r"(r[2]), "=r"(r[3]) : "r"(addr));
}
__device__ __forceinline__ void ldsm2(u32* r, u32 addr) {
    asm volatile("ldmatrix.sync.aligned.m8n8.x2.shared.b16 {%0,%1}, [%2];"
                 : "=r"(r[0]), "=r"(r[1]) : "r"(addr));
}
__device__ __forceinline__ void mma16816(float* d, const u32* a, const u32* b) {
    asm volatile("mma.sync.aligned.m16n8k16.row.col.f32.bf16.bf16.f32 "
                 "{%0,%1,%2,%3}, {%4,%5,%6,%7}, {%8,%9}, {%0,%1,%2,%3};"
                 : "+f"(d[0]), "+f"(d[1]), "+f"(d[2]), "+f"(d[3])
                 : "r"(a[0]), "r"(a[1]), "r"(a[2]), "r"(a[3]), "r"(b[0]), "r"(b[1]));
}

// ---------------- 1) scores + keys + mantissa-band histogram ----------------
// valid score s in (0.5,1): mono = bits|0x80000000 in (0xBF000000, 0xBF800000)
__global__ void score_kernel(const float* __restrict__ obj, u64* __restrict__ keys,
                             u32* __restrict__ hist) {
    int n = blockIdx.x * 256 + threadIdx.x;
    int cell = n >> 2;
    int k = n & 3;
    float o0 = obj[cell*8 + 2*k];
    float o1 = obj[cell*8 + 2*k + 1];
    float m  = fmaxf(o0, o1);
    float e0 = expf(o0 - m);
    float e1 = expf(o1 - m);
    float s  = e1 / (e0 + e1);
    u32 bits = (s > 0.5f) ? __float_as_uint(s) : __float_as_uint(-INFINITY);
    u32 mono = (bits & 0x80000000u) ? ~bits : (bits | 0x80000000u);
    keys[n] = ((u64)mono << 32) | (u32)(~n);   // unique; ties -> lower index first
    if (mono > 0xBF000000u)
        atomicAdd(&hist[(mono - 0xBF000000u) >> 9], 1u);
}

// ---------------- 2) find threshold bin for rank-512 ----------------
__global__ void __launch_bounds__(1024) scan_kernel(u32* __restrict__ hist) {
    __shared__ u32 ps[1024];
    int t = threadIdx.x;
    u32 h[16];
    const uint4* hp = (const uint4*)(hist + t*16);
    #pragma unroll
    for (int v = 0; v < 4; v++) {
        uint4 x = hp[v];
        h[v*4+0] = x.x; h[v*4+1] = x.y; h[v*4+2] = x.z; h[v*4+3] = x.w;
    }
    u32 s = 0;
    #pragma unroll
    for (int k = 0; k < 16; k++) s += h[k];
    ps[1023 - t] = s;                // reversed so prefix => suffix sums
    __syncthreads();
    for (int off = 1; off < 1024; off <<= 1) {
        u32 y = (t >= off) ? ps[t - off] : 0;
        __syncthreads();
        ps[t] += y;
        __syncthreads();
    }
    // ps[i] = sum of segments [1023-i .. 1023]; suffix ss[t] = ps[1023-t]
    u32 inc = ps[1023 - t];
    u32 exc = inc - s;
    if (exc < 512 && inc >= 512) {   // rank-512 boundary in my segment
        u32 c = exc;
        #pragma unroll
        for (int k = 15; k >= 0; k--) {
            c += h[k];
            if (c >= 512) { hist[H_THR] = (u32)(t*16 + k); break; }
        }
    }
    if (t == 0) hist[H_TOT] = ps[1023];   // total valid
}

// ---------------- 3) compact candidates ----------------
__global__ void compact_kernel(const u64* __restrict__ keys, u32* __restrict__ hist,
                               u64* __restrict__ cand) {
    int n = blockIdx.x * 256 + threadIdx.x;
    u64 key = keys[n];
    u32 hi = (u32)(key >> 32);
    bool admit;
    if (hi > 0xBF000000u) admit = ((hi - 0xBF000000u) >> 9) >= hist[H_THR];
    else                  admit = (hist[H_TOT] < 512);   // fallback: too few valid
    if (admit) {
        u32 p = atomicAdd(&hist[H_CNT], 1u);
        if (p < NCAND) cand[p] = key;
    }
}

// ---------------- 4) fused: sort candidates + decode top-512 + IoU + NMS ----------------
__global__ void __launch_bounds__(1024) select_nms_kernel(const u64* __restrict__ cand,
                                                          const u32* __restrict__ hist,
                                                          const float* __restrict__ reg) {
    __shared__ float4 bx[512];
    __shared__ int sval[512];
    __shared__ union { u64 s[NCAND]; u32 msk[512][16]; } u;
    int tid = threadIdx.x, lane = tid & 31, w = tid >> 5;

    u32 cn = hist[H_CNT];
    if (cn > NCAND) cn = NCAND;
    u.s[tid] = (tid < (int)cn) ? cand[tid] : 0ULL;
    __syncthreads();

    // bitonic sort 1024 descending
    for (int k = 2; k <= NCAND; k <<= 1) {
        for (int j = k >> 1; j > 0; j >>= 1) {
            int ixj = tid ^ j;
            if (ixj > tid) {
                u64 a = u.s[tid], b = u.s[ixj];
                bool desc = ((tid & k) == 0);
                if (desc ? (a < b) : (a > b)) { u.s[tid] = b; u.s[ixj] = a; }
            }
            __syncthreads();
        }
    }

    // decode top-512
    if (tid < 512) {
        u64 key = u.s[tid];
        float4 box = make_float4(0.f, 0.f, 0.f, 0.f);
        float score = 0.0f;
        int valid = 0;
        if (key != 0ULL) {
            u32 lo = (u32)key;
            u32 hi = (u32)(key >> 32);
            u32 n  = ~lo;
            u32 fb = (hi & 0x80000000u) ? (hi ^ 0x80000000u) : ~hi;
            float sc = __uint_as_float(fb);
            int k = n & 3;
            int j = (n >> 2) & 127;
            int i = n >> 9;
            float sz = (float)((k + 1) * 32);
            int base = ((i*128 + j) * 16) + k*4;
            float r0 = reg[base+0], r1 = reg[base+1], r2 = reg[base+2], r3 = reg[base+3];
            float acx = j * 16.0f + 8.0f;
            float acy = i * 16.0f + 8.0f;
            float cx = acx + r0 * sz;
            float cy = acy + r1 * sz;
            float ww = sz * expf(r2);
            float hh = sz * expf(r3);
            box = make_float4(cx - ww*0.5f, cy - hh*0.5f, ww, hh);
            valid = (sc > 0.5f) ? 1 : 0;
            score = valid ? sc : 0.0f;
        }
        bx[tid] = box;
        sval[tid] = valid;
        g_sel[tid*4+0] = box.x;
        g_sel[tid*4+1] = box.y;
        g_sel[tid*4+2] = box.z;
        g_sel[tid*4+3] = box.w;
        g_scores[tid] = score;
    }
    __syncthreads();   // s[] dead; msk[] now live (union)

    // IoU bitmask: 32 warps x 16 rows each
    #pragma unroll 1
    for (int r = 0; r < 16; r++) {
        int i = w*16 + r;
        float4 a = bx[i];
        float ax2 = a.x + a.z, ay2 = a.y + a.w, aar = a.z * a.w;
        #pragma unroll 1
        for (int jc = 0; jc < 16; jc++) {
            int j = jc*32 + lane;
            float4 b = bx[j];
            float bx2 = b.x + b.z, by2 = b.y + b.w;
            float ix = fmaxf(0.0f, fminf(ax2, bx2) - fmaxf(a.x, b.x));
            float iy = fmaxf(0.0f, fminf(ay2, by2) - fmaxf(a.y, b.y));
            float inter = ix * iy;
            float iou = inter / (aar + b.z*b.w - inter + 1e-8f);
            u32 bits = __ballot_sync(0xffffffffu, iou > 0.3f);
            if (lane == jc) u.msk[i][jc] = bits;
        }
    }
    __syncthreads();

    // greedy NMS scan (warp 0): lane l<16 owns suppression word l
    if (w == 0) {
        u32 removed = 0;
        for (int i = 0; i < 512; i++) {
            int wi = i >> 5, bi = i & 31;
            u32 rword = __shfl_sync(0xffffffffu, removed, wi);
            int k = sval[i] && !((rword >> bi) & 1u);
            if (lane == 0) g_keep[i] = k;
            if (k && lane < 16) removed |= u.msk[i][lane];
        }
    }
}

// ---------------- 5) ROI align -> bf16 hi/lo ----------------
__global__ void __launch_bounds__(512) roi_kernel(const float* __restrict__ feat) {
    int mrow = blockIdx.x;
    __shared__ float bxs[4];
    __shared__ int   xs0[6], xs1[6], ys0[6], ys1[6];
    __shared__ float wxs[6], wys[6];
    int tid = threadIdx.x;
    if (tid < 4) bxs[tid] = g_sel[mrow*4 + tid];
    __syncthreads();
    if (tid < 6) {
        float t = (tid + 0.5f) / 6.0f;
        float fx = (bxs[0] + t * bxs[2]) / 16.0f - 0.5f;
        float fy = (bxs[1] + t * bxs[3]) / 16.0f - 0.5f;
        fx = fminf(fmaxf(fx, 0.0f), 127.0f);
        fy = fminf(fmaxf(fy, 0.0f), 127.0f);
        int x0 = (int)floorf(fx);
        int y0 = (int)floorf(fy);
        xs0[tid] = x0; xs1[tid] = min(x0 + 1, 127); wxs[tid] = fx - (float)x0;
        ys0[tid] = y0; ys1[tid] = min(y0 + 1, 127); wys[tid] = fy - (float)y0;
    }
    __syncthreads();
    int c = tid;
    float mx[9];
    #pragma unroll
    for (int p = 0; p < 9; p++) mx[p] = -INFINITY;
    #pragma unroll
    for (int ty = 0; ty < 6; ty++) {
        int y0 = ys0[ty], y1 = ys1[ty];
        float wy = wys[ty], wy0 = 1.0f - wy;
        #pragma unroll
        for (int tx = 0; tx < 6; tx++) {
            int x0 = xs0[tx], x1 = xs1[tx];
            float wx = wxs[tx], wx0 = 1.0f - wx;
            float f00 = feat[(y0*128 + x0)*512 + c];
            float f01 = feat[(y0*128 + x1)*512 + c];
            float f10 = feat[(y1*128 + x0)*512 + c];
            float f11 = feat[(y1*128 + x1)*512 + c];
            float v = f00*wy0*wx0 + f01*wy0*wx + f10*wy*wx0 + f11*wy*wx;
            int p = (ty >> 1)*3 + (tx >> 1);
            mx[p] = fmaxf(mx[p], v);
        }
    }
    #pragma unroll
    for (int p = 0; p < 9; p++) {
        float v = mx[p];
        __nv_bfloat16 h = __float2bfloat16(v);
        __nv_bfloat16 l = __float2bfloat16(v - __bfloat162float(h));
        g_Ahi[mrow*PDIM + p*512 + c] = h;
        g_Alo[mrow*PDIM + p*512 + c] = l;
    }
}

// ---------------- 6) weight transpose + hi/lo split ----------------
__global__ void tsplit_kernel(const float* __restrict__ W,
                              __nv_bfloat16* __restrict__ Th,
                              __nv_bfloat16* __restrict__ Tl,
                              int K, int N) {
    __shared__ float t[32][33];
    int n0 = blockIdx.x * 32, k0 = blockIdx.y * 32;
    int tx = threadIdx.x, ty = threadIdx.y;   // 32 x 8
    #pragma unroll
    for (int i = 0; i < 4; i++)
        t[ty + 8*i][tx] = W[(size_t)(k0 + ty + 8*i)*N + n0 + tx];
    __syncthreads();
    #pragma unroll
    for (int i = 0; i < 4; i++) {
        float v = t[tx][ty + 8*i];
        __nv_bfloat16 h = __float2bfloat16(v);
        __nv_bfloat16 l = __float2bfloat16(v - __bfloat162float(h));
        size_t o = (size_t)(n0 + ty + 8*i)*K + k0 + tx;
        Th[o] = h;
        Tl[o] = l;
    }
}

// ---------------- 7) HMMA bf16x3 GEMM: C = relu(A@B^T + bias) -> bf16 hi/lo ----------------
#define BM 64
#define BN 64
#define BK 32
#define SSTR 40
#define AH0 0
#define AL0 (64*SSTR)
#define BH0 (128*SSTR)
#define BL0 (192*SSTR)
#define BUFE (256*SSTR)
#define BUFB (BUFE*2)          // 20480 bytes
#define GEMM_SMEM (2*BUFB)     // 40960 bytes

__device__ __forceinline__ void gemm_load_chunk(u32 smbase, int buf,
    const __nv_bfloat16* __restrict__ Ah, const __nv_bfloat16* __restrict__ Al,
    const __nv_bfloat16* __restrict__ Bh, const __nv_bfloat16* __restrict__ Bl,
    int br, int bc, int K, int k0, int tid)
{
    u32 base = smbase + (u32)buf * BUFB;
    int row = tid >> 2;
    int cg  = (tid & 3) * 8;
    CPA16(base + (u32)(AH0 + row*SSTR + cg)*2, Ah + (size_t)(br+row)*K + k0 + cg);
    CPA16(base + (u32)(AL0 + row*SSTR + cg)*2, Al + (size_t)(br+row)*K + k0 + cg);
    CPA16(base + (u32)(BH0 + row*SSTR + cg)*2, Bh + (size_t)(bc+row)*K + k0 + cg);
    CPA16(base + (u32)(BL0 + row*SSTR + cg)*2, Bl + (size_t)(bc+row)*K + k0 + cg);
    CPA_COMMIT();
}

__global__ void __launch_bounds__(256) hgemm_kernel(
    const __nv_bfloat16* __restrict__ Ah, const __nv_bfloat16* __restrict__ Al,
    const __nv_bfloat16* __restrict__ Bh, const __nv_bfloat16* __restrict__ Bl,
    const float* __restrict__ bias,
    __nv_bfloat16* __restrict__ Chi, __nv_bfloat16* __restrict__ Clo,
    int K, int ldc, int do_relu)
{
    extern __shared__ __nv_bfloat16 sm[];
    u32 smbase = smem_u32(sm);
    int tid = threadIdx.x;
    int lane = tid & 31;
    int w = tid >> 5;
    int br = blockIdx.y * BM;
    int bc = blockIdx.x * BN;
    int wm = (w >> 2) * 32;
    int wn = (w & 3) * 16;

    float acc[2][2][4];
    #pragma unroll
    for (int mt = 0; mt < 2; mt++)
        #pragma unroll
        for (int nt = 0; nt < 2; nt++)
            #pragma unroll
            for (int e = 0; e < 4; e++) acc[mt][nt][e] = 0.0f;

    const int NC = K / BK;
    gemm_load_chunk(smbase, 0, Ah, Al, Bh, Bl, br, bc, K, 0, tid);

    for (int c = 0; c < NC; c++) {
        CPA_WAIT0();
        __syncthreads();
        if (c + 1 < NC)
            gemm_load_chunk(smbase, (c+1) & 1, Ah, Al, Bh, Bl, br, bc, K, (c+1)*BK, tid);

        u32 base = smbase + (u32)(c & 1) * BUFB;
        #pragma unroll
        for (int ks = 0; ks < BK; ks += 16) {
            u32 afr[2][4], afl[2][4], bfr[2][2], bfl[2][2];
            #pragma unroll
            for (int mt = 0; mt < 2; mt++) {
                u32 ra = base + (u32)(AH0 + (wm + mt*16 + (lane & 15))*SSTR
                                       + ks + (lane >> 4)*8)*2;
                ldsm4(afr[mt], ra);
                ldsm4(afl[mt], ra + (u32)(AL0 - AH0)*2);
            }
            #pragma unroll
            for (int nt = 0; nt < 2; nt++) {
                u32 rb = base + (u32)(BH0 + (wn + nt*8 + (lane & 7))*SSTR
                                       + ks + ((lane >> 3) & 1)*8)*2;
                ldsm2(bfr[nt], rb);
                ldsm2(bfl[nt], rb + (u32)(BL0 - BH0)*2);
            }
            #pragma unroll
            for (int mt = 0; mt < 2; mt++)
                #pragma unroll
                for (int nt = 0; nt < 2; nt++) {
                    mma16816(acc[mt][nt], afr[mt], bfr[nt]);
                    mma16816(acc[mt][nt], afr[mt], bfl[nt]);
                    mma16816(acc[mt][nt], afl[mt], bfr[nt]);
                }
        }
        __syncthreads();
    }

    int g  = lane >> 2;
    int tg = lane & 3;
    #pragma unroll
    for (int mt = 0; mt < 2; mt++) {
        #pragma unroll
        for (int nt = 0; nt < 2; nt++) {
            int row0 = br + wm + mt*16 + g;
            int col0 = bc + wn + nt*8 + 2*tg;
            #pragma unroll
            for (int e = 0; e < 4; e++) {
                int row = row0 + (e >> 1)*8;
                int col = col0 + (e & 1);
                float v = acc[mt][nt][e] + bias[col];
                if (do_relu) v = fmaxf(v, 0.0f);
                __nv_bfloat16 h = __float2bfloat16(v);
                __nv_bfloat16 l = __float2bfloat16(v - __bfloat162float(h));
                Chi[(size_t)row*ldc + col] = h;
                Clo[(size_t)row*ldc + col] = l;
            }
        }
    }
}

// ---------------- 8) FC3 + unparameterize + keep gate ----------------
__global__ void fc3_final_kernel(const float* __restrict__ W3,
                                 const float* __restrict__ b3,
                                 float* __restrict__ out) {
    int mrow = blockIdx.x;
    int tid = threadIdx.x;     // 128
    float acc[4] = {0,0,0,0};
    for (int k = tid; k < HIDDEN; k += 128) {
        float hv = __bfloat162float(g_h2hi[mrow*HIDDEN + k]) +
                   __bfloat162float(g_h2lo[mrow*HIDDEN + k]);
        #pragma unroll
        for (int c = 0; c < 4; c++) acc[c] = fmaf(hv, W3[k*4 + c], acc[c]);
    }
    __shared__ float red[4][128];
    #pragma unroll
    for (int c = 0; c < 4; c++) red[c][tid] = acc[c];
    __syncthreads();
    for (int s = 64; s > 0; s >>= 1) {
        if (tid < s) {
            #pragma unroll
            for (int c = 0; c < 4; c++) red[c][tid] += red[c][tid + s];
        }
        __syncthreads();
    }
    if (tid == 0) {
        if (!g_keep[mrow]) {
            #pragma unroll
            for (int c = 0; c < 5; c++) out[mrow*5 + c] = 0.0f;
        } else {
            float d0 = red[0][0] + b3[0];
            float d1 = red[1][0] + b3[1];
            float d2 = red[2][0] + b3[2];
            float d3 = red[3][0] + b3[3];
            float sx = g_sel[mrow*4+0], sy = g_sel[mrow*4+1];
            float sw = g_sel[mrow*4+2], sh = g_sel[mrow*4+3];
            float acx = sx + sw * 0.5f;
            float acy = sy + sh * 0.5f;
            float cx = acx + d0 * sw;
            float cy = acy + d1 * sh;
            float w  = sw * expf(d2);
            float h  = sh * expf(d3);
            out[mrow*5+0] = cx - w * 0.5f;
            out[mrow*5+1] = cy - h * 0.5f;
            out[mrow*5+2] = w;
            out[mrow*5+3] = h;
            out[mrow*5+4] = g_scores[mrow];
        }
    }
}

// ---------------- launch ----------------
extern "C" void kernel_launch(void* const* d_in, const int* in_sizes, int n_in,
                              void* d_out, int out_size) {
    const float* features = (const float*)d_in[0];
    const float* rpn_obj  = (const float*)d_in[1];
    const float* rpn_reg  = (const float*)d_in[2];
    const float* W1 = (const float*)d_in[4];
    const float* b1 = (const float*)d_in[5];
    const float* W2 = (const float*)d_in[6];
    const float* b2 = (const float*)d_in[7];
    const float* W3 = (const float*)d_in[8];
    const float* b3 = (const float*)d_in[9];
    float* out = (float*)d_out;

    u64 *keys, *cand;
    u32 *hist;
    __nv_bfloat16 *Ahi, *Alo, *W1Th, *W1Tl, *W2Th, *W2Tl, *h1hi, *h1lo, *h2hi, *h2lo;
    cudaGetSymbolAddress((void**)&keys, g_keys);
    cudaGetSymbolAddress((void**)&cand, g_cand);
    cudaGetSymbolAddress((void**)&hist, g_hist);
    cudaGetSymbolAddress((void**)&Ahi, g_Ahi);
    cudaGetSymbolAddress((void**)&Alo, g_Alo);
    cudaGetSymbolAddress((void**)&W1Th, g_W1Th);
    cudaGetSymbolAddress((void**)&W1Tl, g_W1Tl);
    cudaGetSymbolAddress((void**)&W2Th, g_W2Th);
    cudaGetSymbolAddress((void**)&W2Tl, g_W2Tl);
    cudaGetSymbolAddress((void**)&h1hi, g_h1hi);
    cudaGetSymbolAddress((void**)&h1lo, g_h1lo);
    cudaGetSymbolAddress((void**)&h2hi, g_h2hi);
    cudaGetSymbolAddress((void**)&h2lo, g_h2lo);

    cudaFuncSetAttribute(hgemm_kernel,
                         cudaFuncAttributeMaxDynamicSharedMemorySize, GEMM_SMEM);

    cudaMemsetAsync(hist, 0, (NBIN + 8) * sizeof(u32));

    // weight prep (independent of detection path)
    tsplit_kernel<<<dim3(HIDDEN/32, PDIM/32),   dim3(32,8)>>>(W1, W1Th, W1Tl, PDIM,   HIDDEN);
    tsplit_kernel<<<dim3(HIDDEN/32, HIDDEN/32), dim3(32,8)>>>(W2, W2Th, W2Tl, HIDDEN, HIDDEN);

    score_kernel<<<NA/256, 256>>>(rpn_obj, keys, hist);
    scan_kernel<<<1, 1024>>>(hist);
    compact_kernel<<<NA/256, 256>>>(keys, hist, cand);
    select_nms_kernel<<<1, 1024>>>(cand, hist, rpn_reg);

    roi_kernel<<<512, 512>>>(features);

    dim3 gg(HIDDEN/BN, MAXDET/BM);   // 16 x 8 = 128 CTAs
    hgemm_kernel<<<gg, 256, GEMM_SMEM>>>(Ahi,  Alo,  W1Th, W1Tl, b1, h1hi, h1lo,
                                         PDIM,   HIDDEN, 1);
    hgemm_kernel<<<gg, 256, GEMM_SMEM>>>(h1hi, h1lo, W2Th, W2Tl, b2, h2hi, h2lo,
                                         HIDDEN, HIDDEN, 1);
    fc3_final_kernel<<<MAXDET, 128>>>(W3, b3, out);
}